// round 7
// baseline (speedup 1.0000x reference)
#include <cuda_runtime.h>
#include <cstdint>

typedef unsigned long long ull;

static constexpr int B_  = 1024;
static constexpr int T_  = 512;
static constexpr int DIN = 128;
static constexpr int H_  = 64;
static constexpr int O_  = 20;
static constexpr int R_  = B_ * T_;        // 524288 rows

// Scratch (padded for unconditional prefetch rings)
__device__ float g_cur1[(size_t)(R_ + 16) * H_];
__device__ float g_cur2[(size_t)(R_ + 16) * H_];
__device__ ull   g_mask1[R_ + 16];
__device__ ull   g_mask2[R_ + 16];

// ---------------------------------------------------------------------------
// helpers
// ---------------------------------------------------------------------------
__device__ __forceinline__ uint32_t smem_u32(const void* p) {
    uint32_t a;
    asm("{ .reg .u64 t; cvta.to.shared.u64 t, %1; cvt.u32.u64 %0, t; }"
        : "=r"(a) : "l"(p));
    return a;
}
__device__ __forceinline__ ull pack2f(float x, float y) {
    ull d; asm("mov.b64 %0, {%1,%2};" : "=l"(d) : "f"(x), "f"(y)); return d;
}
__device__ __forceinline__ void addf2(ull& d, ull a, ull b) {
    asm("add.rn.f32x2 %0, %1, %2;" : "=l"(d) : "l"(a), "l"(b));
}
__device__ __forceinline__ uint32_t pack_bf16x2(float lo, float hi) {
    uint32_t r;
    asm("cvt.rn.satfinite.bf16x2.f32 %0, %2, %1;" : "=r"(r) : "f"(lo), "f"(hi));
    return r;
}
__device__ __forceinline__ void ldsm4(uint32_t* r, uint32_t addr) {
    asm volatile("ldmatrix.sync.aligned.m8n8.x4.shared.b16 {%0,%1,%2,%3}, [%4];"
                 : "=r"(r[0]), "=r"(r[1]), "=r"(r[2]), "=r"(r[3]) : "r"(addr));
}
__device__ __forceinline__ void mma16816(float* c, const uint32_t* a,
                                         const uint32_t* b) {
    asm volatile(
        "mma.sync.aligned.m16n8k16.row.col.f32.bf16.bf16.f32 "
        "{%0,%1,%2,%3}, {%4,%5,%6,%7}, {%8,%9}, {%0,%1,%2,%3};"
        : "+f"(c[0]), "+f"(c[1]), "+f"(c[2]), "+f"(c[3])
        : "r"(a[0]), "r"(a[1]), "r"(a[2]), "r"(a[3]), "r"(b[0]), "r"(b[1]));
}
__device__ __forceinline__ float clip01(float v) {
    return fminf(fmaxf(v, 0.f), 1.f);
}

// ---------------------------------------------------------------------------
// Kernel 1: layer-1 GEMM via HMMA (mma.sync m16n8k16 bf16, fp32 acc),
// 3-term bf16 split. UNCHANGED from the 287us kernel.
// ---------------------------------------------------------------------------
static constexpr int SROW = 136;
static constexpr int AH_OFF = 0;
static constexpr int AL_OFF = 128 * (SROW / 2);
static constexpr int BH_OFF = 2 * AL_OFF;
static constexpr int BL_OFF = BH_OFF + 64 * (SROW / 2);
static constexpr int GEMM_WORDS = BL_OFF + 64 * (SROW / 2);
static constexpr int GEMM_SMEM  = GEMM_WORDS * 4;

__global__ void __launch_bounds__(256) snn_gemm_mma(
    const float* __restrict__ x,
    const float* __restrict__ W1,
    const float* __restrict__ b1)
{
    extern __shared__ uint32_t sm[];
    __shared__ float b1s[64];

    const int tid  = threadIdx.x;
    const int lane = tid & 31;
    const int wid  = tid >> 5;
    const size_t rbase = (size_t)blockIdx.x * 128;

    if (tid < 64) b1s[tid] = b1[tid];

#pragma unroll
    for (int it = 0; it < 16; it++) {
        int idx = it * 256 + tid;
        int row = idx >> 5;
        int c4  = idx & 31;
        float4 v = *reinterpret_cast<const float4*>(x + (rbase + row) * DIN + c4 * 4);
        uint32_t h01 = pack_bf16x2(v.x, v.y);
        uint32_t h23 = pack_bf16x2(v.z, v.w);
        float h0 = __uint_as_float(h01 << 16), h1 = __uint_as_float(h01 & 0xffff0000u);
        float h2 = __uint_as_float(h23 << 16), h3 = __uint_as_float(h23 & 0xffff0000u);
        uint32_t l01 = pack_bf16x2(v.x - h0, v.y - h1);
        uint32_t l23 = pack_bf16x2(v.z - h2, v.w - h3);
        int w = row * (SROW / 2) + c4 * 2;
        *reinterpret_cast<ull*>(&sm[AH_OFF + w]) = ((ull)h23 << 32) | h01;
        *reinterpret_cast<ull*>(&sm[AL_OFF + w]) = ((ull)l23 << 32) | l01;
    }
#pragma unroll
    for (int it = 0; it < 8; it++) {
        int idx = it * 256 + tid;
        int row = idx >> 5;
        int c4  = idx & 31;
        float4 v = *reinterpret_cast<const float4*>(W1 + (size_t)row * DIN + c4 * 4);
        uint32_t h01 = pack_bf16x2(v.x, v.y);
        uint32_t h23 = pack_bf16x2(v.z, v.w);
        float h0 = __uint_as_float(h01 << 16), h1 = __uint_as_float(h01 & 0xffff0000u);
        float h2 = __uint_as_float(h23 << 16), h3 = __uint_as_float(h23 & 0xffff0000u);
        uint32_t l01 = pack_bf16x2(v.x - h0, v.y - h1);
        uint32_t l23 = pack_bf16x2(v.z - h2, v.w - h3);
        int w = row * (SROW / 2) + c4 * 2;
        *reinterpret_cast<ull*>(&sm[BH_OFF + w]) = ((ull)h23 << 32) | h01;
        *reinterpret_cast<ull*>(&sm[BL_OFF + w]) = ((ull)l23 << 32) | l01;
    }
    __syncthreads();

    const uint32_t sbase = smem_u32(sm);
    const int m0  = wid * 16;
    const int mat = lane >> 3, mr = lane & 7;
    const uint32_t aoff = (uint32_t)((m0 + (mat & 1) * 8 + mr) * SROW +
                                     (mat >> 1) * 8) * 2;
    const uint32_t boff = (uint32_t)(((mat >> 1) * 8 + mr) * SROW +
                                     (mat & 1) * 8) * 2;

    float acc[8][4];
#pragma unroll
    for (int i = 0; i < 8; i++)
#pragma unroll
        for (int j = 0; j < 4; j++) acc[i][j] = 0.f;

    const uint32_t Abase[3] = { sbase + AH_OFF * 4, sbase + AH_OFF * 4,
                                sbase + AL_OFF * 4 };
    const uint32_t Bbase[3] = { sbase + BH_OFF * 4, sbase + BL_OFF * 4,
                                sbase + BH_OFF * 4 };

#pragma unroll
    for (int t = 0; t < 3; t++) {
        const uint32_t aB = Abase[t] + aoff;
        const uint32_t bB = Bbase[t] + boff;
#pragma unroll
        for (int kc = 0; kc < 8; kc++) {
            uint32_t a[4];
            ldsm4(a, aB + kc * 32);
#pragma unroll
            for (int np = 0; np < 4; np++) {
                uint32_t b[4];
                ldsm4(b, bB + (uint32_t)(np * 16 * SROW) * 2 + kc * 32);
                mma16816(acc[np * 2 + 0], a, b + 0);
                mma16816(acc[np * 2 + 1], a, b + 2);
            }
        }
    }

    const int g = lane >> 2, q = lane & 3;
#pragma unroll
    for (int np = 0; np < 4; np++) {
#pragma unroll
        for (int h = 0; h < 2; h++) {
            const float* a4 = acc[np * 2 + h];
            int col = np * 16 + h * 8 + 2 * q;
            float2 bv = *reinterpret_cast<const float2*>(&b1s[col]);
            float2 o0 = make_float2(a4[0] + bv.x, a4[1] + bv.y);
            float2 o1 = make_float2(a4[2] + bv.x, a4[3] + bv.y);
            float* d0 = g_cur1 + (rbase + m0 + g) * H_ + col;
            float* d1 = g_cur1 + (rbase + m0 + g + 8) * H_ + col;
            *reinterpret_cast<float2*>(d0) = o0;
            *reinterpret_cast<float2*>(d1) = o1;
        }
    }
}

// ---------------------------------------------------------------------------
// Kernel 2/4: parallel LIF scan. One warp per (batch, 32-neuron half).
// 2048 independent warps, each runs the 512-step membrane recurrence for its
// 32 neurons and ballots the spike bits into g_mask[r] (its u32 half).
// ---------------------------------------------------------------------------
__global__ void __launch_bounds__(256) snn_lif(
    const float* __restrict__ cur, const float* __restrict__ beta,
    ull* __restrict__ maskout)
{
    const int tid  = threadIdx.x;
    const int lane = tid & 31;
    const int w    = blockIdx.x * 8 + (tid >> 5);
    const int b    = w >> 1;
    const int half = w & 1;
    const int n    = half * 32 + lane;

    const float bt = clip01(beta[n]);
    const float* src = cur + (size_t)b * T_ * H_ + n;
    uint32_t* mdst = reinterpret_cast<uint32_t*>(maskout + (size_t)b * T_) + half;

    float m = 0.f, r = 0.f;
    float ring[8];
#pragma unroll
    for (int i = 0; i < 8; i++) ring[i] = src[i * H_];

#pragma unroll 8
    for (int t = 0; t < T_; t++) {
        const int s = t & 7;
        float c = ring[s];
        ring[s] = src[(size_t)(t + 8) * H_];      // padded array: safe overread
        m = fmaf(bt, m, c) - r;
        bool sp = m > 1.f;
        r = sp ? 1.f : 0.f;
        unsigned mk = __ballot_sync(0xffffffffu, sp);
        if (lane == 0) mdst[(size_t)t * 2] = mk;
    }
}

// ---------------------------------------------------------------------------
// Kernel 3: parallel layer-2 gather. cur2[r][:] = b2 + sum_{i in mask1[r]} W2[:,i]
// Warp per row, 64 rows per warp serially; masks via broadcast LDG.64 ring.
// W2 pair-packed in smem: sW2P[i][lane] = (W2[2l][i], W2[2l+1][i]) -> STG.64.
// ---------------------------------------------------------------------------
__global__ void __launch_bounds__(256) snn_gather2(
    const ull* __restrict__ mask1, const float* __restrict__ W2,
    const float* __restrict__ b2, float* __restrict__ cur2)
{
    __shared__ ull sW2P[64 * 32];

    const int tid  = threadIdx.x;
    const int lane = tid & 31;
    const int wid  = tid >> 5;

    for (int idx = tid; idx < 64 * 32; idx += 256) {
        int i = idx >> 5, l = idx & 31;
        sW2P[idx] = pack2f(W2[(2 * l) * 64 + i], W2[(2 * l + 1) * 64 + i]);
    }
    __syncthreads();

    const ull b2p = pack2f(b2[2 * lane], b2[2 * lane + 1]);
    const size_t r0 = ((size_t)blockIdx.x * 8 + wid) * 64;
    const ull* mp = mask1 + r0;
    float* dst = cur2 + r0 * H_ + 2 * lane;

    ull ring[4];
#pragma unroll
    for (int i = 0; i < 4; i++) ring[i] = mp[i];

#pragma unroll 4
    for (int j = 0; j < 64; j++) {
        ull mk = ring[j & 3];
        ring[j & 3] = mp[j + 4];                  // padded: safe overread
        ull acc = b2p;
        while (mk) {
            int i = __ffsll((long long)mk) - 1;
            mk &= mk - 1;
            addf2(acc, acc, sW2P[(i << 5) + lane]);
        }
        *reinterpret_cast<ull*>(dst + (size_t)j * H_) = acc;
    }
}

// ---------------------------------------------------------------------------
// Kernel 5: fused layer-3 gather + leaky integration (no reset).
// One warp per batch; per step: broadcast mask2, tiny sparse gather, fma, store.
// ---------------------------------------------------------------------------
__global__ void __launch_bounds__(256) snn_out3(
    const ull* __restrict__ mask2, const float* __restrict__ W3,
    const float* __restrict__ b3, const float* __restrict__ beta3,
    float* __restrict__ out)
{
    __shared__ float sW3T[64 * 32];   // [i][o]; cols >= 20 are 0

    const int tid  = threadIdx.x;
    const int lane = tid & 31;
    const int wid  = tid >> 5;
    const int b    = blockIdx.x * 8 + wid;

    for (int idx = tid; idx < 64 * 32; idx += 256) sW3T[idx] = 0.f;
    __syncthreads();
    for (int idx = tid; idx < O_ * 64; idx += 256) {
        int o = idx >> 6, i = idx & 63;
        sW3T[i * 32 + o] = W3[idx];
    }
    __syncthreads();

    const float bt3 = (lane < O_) ? clip01(beta3[lane]) : 0.f;
    const float b3v = (lane < O_) ? b3[lane] : 0.f;

    const ull* mp = mask2 + (size_t)b * T_;
    float* dst = out + (size_t)b * T_ * O_;

    float m3 = 0.f;
    ull ring[8];
#pragma unroll
    for (int i = 0; i < 8; i++) ring[i] = mp[i];

#pragma unroll 8
    for (int t = 0; t < T_; t++) {
        ull mk = ring[t & 7];
        ring[t & 7] = mp[t + 8];                  // padded: safe overread
        float acc = b3v;
        while (mk) {
            int i = __ffsll((long long)mk) - 1;
            mk &= mk - 1;
            acc += sW3T[(i << 5) + lane];
        }
        m3 = fmaf(bt3, m3, acc);
        if (lane < O_) dst[(size_t)t * O_ + lane] = m3;
    }
}

// ---------------------------------------------------------------------------
// Launch
// ---------------------------------------------------------------------------
extern "C" void kernel_launch(void* const* d_in, const int* in_sizes, int n_in,
                              void* d_out, int out_size)
{
    const float* x     = (const float*)d_in[0];
    const float* W1    = (const float*)d_in[1];
    const float* b1    = (const float*)d_in[2];
    const float* beta1 = (const float*)d_in[3];
    const float* W2    = (const float*)d_in[4];
    const float* b2    = (const float*)d_in[5];
    const float* beta2 = (const float*)d_in[6];
    const float* W3    = (const float*)d_in[7];
    const float* b3    = (const float*)d_in[8];
    const float* beta3 = (const float*)d_in[9];
    float* out = (float*)d_out;

    float *cur1, *cur2;
    ull *mask1, *mask2;
    cudaGetSymbolAddress((void**)&cur1,  g_cur1);
    cudaGetSymbolAddress((void**)&cur2,  g_cur2);
    cudaGetSymbolAddress((void**)&mask1, g_mask1);
    cudaGetSymbolAddress((void**)&mask2, g_mask2);

    cudaFuncSetAttribute(snn_gemm_mma,
                         cudaFuncAttributeMaxDynamicSharedMemorySize, GEMM_SMEM);
    snn_gemm_mma<<<R_ / 128, 256, GEMM_SMEM>>>(x, W1, b1);
    snn_lif<<<256, 256>>>(cur1, beta1, mask1);
    snn_gather2<<<1024, 256>>>(mask1, W2, b2, cur2);
    snn_lif<<<256, 256>>>(cur2, beta2, mask2);
    snn_out3<<<128, 256>>>(mask2, W3, b3, beta3, out);
}